// round 2
// baseline (speedup 1.0000x reference)
#include <cuda_runtime.h>
#include <math.h>

#define NN    50000
#define NE    800000
#define INF_  32
#define H     64
#define HV    16      // H/4 (float4 lanes per row)
#define EDIM  4
#define NL    3
#define NG    512
#define NOUT  2
#define NPAD  50016   // 1563 * 32
#define BN_EPS 1e-5f
#define PN_EPS 1e-5f

// ---------------- persistent device scratch (zero-initialized at load) -----
__device__ float d_h[NPAD * H];
__device__ float d_agg[NPAD * H];
__device__ float d_gsum[NG * H];
__device__ float d_gss[NG];
__device__ float d_gcnt[NG];
__device__ float d_mean[NG * H];
__device__ float d_invd[NG];
__device__ float d_pool[NG * H];

// 16-byte vector reduction to global (sm_90+)
__device__ __forceinline__ void red_add4(float4* a, float4 v) {
    asm volatile("red.global.add.v4.f32 [%0], {%1,%2,%3,%4};"
                 :: "l"(a), "f"(v.x), "f"(v.y), "f"(v.z), "f"(v.w) : "memory");
}

__device__ __forceinline__ float4 f4zero() { return make_float4(0.f, 0.f, 0.f, 0.f); }

__device__ __forceinline__ void f4fma(float4& acc, float s, const float4 w) {
    acc.x = fmaf(s, w.x, acc.x);
    acc.y = fmaf(s, w.y, acc.y);
    acc.z = fmaf(s, w.z, acc.z);
    acc.w = fmaf(s, w.w, acc.w);
}

__device__ __forceinline__ float4 f4relu_add(float4 a, float4 b) {
    return make_float4(fmaxf(a.x + b.x, 0.f), fmaxf(a.y + b.y, 0.f),
                       fmaxf(a.z + b.z, 0.f), fmaxf(a.w + b.w, 0.f));
}

// ---------------- counts: batch is sorted -> binary search per graph -------
__global__ void count_kernel(const int* __restrict__ batch) {
    int g = blockIdx.x * blockDim.x + threadIdx.x;
    if (g >= NG) return;
    int lo = 0, hi = NN;
    while (lo < hi) { int m = (lo + hi) >> 1; if (batch[m] < g) lo = m + 1; else hi = m; }
    int s = lo;
    lo = 0; hi = NN;
    while (lo < hi) { int m = (lo + hi) >> 1; if (batch[m] < g + 1) lo = m + 1; else hi = m; }
    d_gcnt[g] = fmaxf((float)(lo - s), 1.0f);
}

// ---------------- input linear: h = x @ W_in + b ; also zeroes d_agg -------
__global__ void __launch_bounds__(256) lin_in_kernel(const float* __restrict__ x,
                                                     const float* __restrict__ W,
                                                     const float* __restrict__ b) {
    __shared__ __align__(16) float4 Ws[INF_ * HV];
    __shared__ __align__(16) float4 bs[HV];
    int t = threadIdx.x;
    for (int j = t; j < INF_ * HV; j += 256) Ws[j] = ((const float4*)W)[j];
    if (t < HV) bs[t] = ((const float4*)b)[t];
    __syncthreads();

    int lane = t & 15, rloc = t >> 4;
    int row = blockIdx.x * 16 + rloc;       // row < NPAD always (3126*16 = 50016)

    ((float4*)d_agg)[row * HV + lane] = f4zero();   // zero agg for layer 0

    if (row < NN) {
        float4 acc = bs[lane];
        const float* xr = x + row * INF_;
        #pragma unroll
        for (int k = 0; k < INF_; k++) {
            float xv = __ldg(xr + k);
            f4fma(acc, xv, Ws[k * HV + lane]);
        }
        ((float4*)d_h)[row * HV + lane] = acc;
    }
}

// ---------------- edge kernel: agg[dst] += relu(h[src] + ea @ We + be) ------
__global__ void __launch_bounds__(256) edge_kernel(const int* __restrict__ ei,
                                                   const float* __restrict__ eattr,
                                                   const float* __restrict__ eW,
                                                   const float* __restrict__ eb) {
    __shared__ __align__(16) float4 Ws[EDIM * HV];
    __shared__ __align__(16) float4 bs[HV];
    int t = threadIdx.x;
    if (t < EDIM * HV) Ws[t] = ((const float4*)eW)[t];
    if (t < HV) bs[t] = ((const float4*)eb)[t];
    __syncthreads();

    int e    = blockIdx.x * 16 + (t >> 4);  // exactly NE = 50000*16 edges
    int lane = t & 15;
    int src = __ldg(ei + e);
    int dst = __ldg(ei + NE + e);
    float4 a = __ldg((const float4*)eattr + e);

    float4 v = bs[lane];
    f4fma(v, a.x, Ws[0 * HV + lane]);
    f4fma(v, a.y, Ws[1 * HV + lane]);
    f4fma(v, a.z, Ws[2 * HV + lane]);
    f4fma(v, a.w, Ws[3 * HV + lane]);

    float4 hv = __ldg((const float4*)d_h + src * HV + lane);
    float4 m = f4relu_add(v, hv);
    red_add4((float4*)d_agg + dst * HV + lane, m);
}

// ---------------- fused node MLP (+BN folded) + PairNorm stats -------------
// z = (1+eps)*h + agg ; t = relu(BN1(z@W1+b1)) ; h' = relu(BN2(t@W2+b2))
__global__ void __launch_bounds__(256) mlp_kernel(
    const float* __restrict__ W1, const float* __restrict__ b1,
    const float* __restrict__ g1, const float* __restrict__ be1,
    const float* __restrict__ rm1, const float* __restrict__ rv1,
    const float* __restrict__ W2, const float* __restrict__ b2,
    const float* __restrict__ g2, const float* __restrict__ be2,
    const float* __restrict__ rm2, const float* __restrict__ rv2,
    const float* __restrict__ epsp, const int* __restrict__ batch, int do_pn)
{
    __shared__ __align__(16) float W1s[H * H];
    __shared__ __align__(16) float W2s[H * H];
    __shared__ __align__(16) float zs[32][H];
    __shared__ float s1s[H], bb1[H], s2s[H], bb2[H];

    int t = threadIdx.x;
    if (t < H) {
        float s1 = g1[t] * rsqrtf(rv1[t] + BN_EPS);
        s1s[t] = s1;
        bb1[t] = b1[t] * s1 + be1[t] - rm1[t] * s1;
        float s2 = g2[t] * rsqrtf(rv2[t] + BN_EPS);
        s2s[t] = s2;
        bb2[t] = b2[t] * s2 + be2[t] - rm2[t] * s2;
    }
    __syncthreads();
    for (int j = t; j < H * H; j += 256) {
        int c = j & 63;
        W1s[j] = W1[j] * s1s[c];
        W2s[j] = W2[j] * s2s[c];
    }

    // stage z = (1+eps)*h + agg for 32 rows; re-zero agg for next layer
    float epv = 1.0f + epsp[0];
    int R0 = blockIdx.x * 32;
    for (int j = t; j < 32 * HV; j += 256) {
        int r = j >> 4, ln = j & 15;
        int gi = (R0 + r) * HV + ln;
        float4 hv = ((const float4*)d_h)[gi];
        float4 av = ((const float4*)d_agg)[gi];
        float4 z = make_float4(fmaf(epv, hv.x, av.x), fmaf(epv, hv.y, av.y),
                               fmaf(epv, hv.z, av.z), fmaf(epv, hv.w, av.w));
        *(float4*)&zs[r][ln * 4] = z;
        if (do_pn) ((float4*)d_agg)[gi] = f4zero();
    }
    __syncthreads();

    int c4 = t & 15, rp = t >> 4;
    int r0 = rp * 2, r1 = r0 + 1;

    // GEMM1 (BN1 folded into W1s/bb1) + ReLU
    float4 a0 = f4zero(), a1 = f4zero();
    #pragma unroll
    for (int k = 0; k < H; k++) {
        float z0 = zs[r0][k], z1 = zs[r1][k];
        float4 w = *(const float4*)&W1s[k * H + c4 * 4];
        f4fma(a0, z0, w);
        f4fma(a1, z1, w);
    }
    float4 bv1 = *(const float4*)&bb1[c4 * 4];
    float4 t0 = f4relu_add(a0, bv1);
    float4 t1 = f4relu_add(a1, bv1);
    __syncthreads();                         // everyone done reading zs
    *(float4*)&zs[r0][c4 * 4] = t0;
    *(float4*)&zs[r1][c4 * 4] = t1;
    __syncthreads();

    // GEMM2 (BN2 folded) + ReLU
    a0 = f4zero(); a1 = f4zero();
    #pragma unroll
    for (int k = 0; k < H; k++) {
        float z0 = zs[r0][k], z1 = zs[r1][k];
        float4 w = *(const float4*)&W2s[k * H + c4 * 4];
        f4fma(a0, z0, w);
        f4fma(a1, z1, w);
    }
    float4 bv2 = *(const float4*)&bb2[c4 * 4];
    float4 h0 = f4relu_add(a0, bv2);
    float4 h1 = f4relu_add(a1, bv2);

    int row0 = R0 + r0, row1 = R0 + r1;
    if (row0 < NN) ((float4*)d_h)[row0 * HV + c4] = h0;
    if (row1 < NN) ((float4*)d_h)[row1 * HV + c4] = h1;

    if (do_pn) {
        int gg0 = (row0 < NN) ? batch[row0] : 0;
        int gg1 = (row1 < NN) ? batch[row1] : 0;
        if (row0 < NN) red_add4(&((float4*)d_gsum)[gg0 * HV + c4], h0);
        if (row1 < NN) red_add4(&((float4*)d_gsum)[gg1 * HV + c4], h1);
        float v0 = (row0 < NN) ? (h0.x*h0.x + h0.y*h0.y + h0.z*h0.z + h0.w*h0.w) : 0.f;
        float v1 = (row1 < NN) ? (h1.x*h1.x + h1.y*h1.y + h1.z*h1.z + h1.w*h1.w) : 0.f;
        #pragma unroll
        for (int o = 1; o < 16; o <<= 1) {
            v0 += __shfl_xor_sync(0xffffffffu, v0, o);
            v1 += __shfl_xor_sync(0xffffffffu, v1, o);
        }
        if (c4 == 0) {
            if (row0 < NN) atomicAdd(&d_gss[gg0], v0);
            if (row1 < NN) atomicAdd(&d_gss[gg1], v1);
        }
    }
}

// ---------------- PairNorm per-graph mean & inverse denom; self-re-zeros ---
__global__ void meaninv_kernel() {
    int g = blockIdx.x, c = threadIdx.x;     // 64 threads
    float cnt = d_gcnt[g];
    float s = d_gsum[g * H + c];
    d_gsum[g * H + c] = 0.f;
    float mean = s / cnt;
    d_mean[g * H + c] = mean;
    float part = mean * s;                    // sum_c (sum_h_c)^2 / cnt
    #pragma unroll
    for (int o = 16; o; o >>= 1) part += __shfl_down_sync(0xffffffffu, part, o);
    __shared__ float red[2];
    if ((c & 31) == 0) red[c >> 5] = part;
    __syncthreads();
    if (c == 0) {
        float ss = d_gss[g];
        d_gss[g] = 0.f;
        float var = (ss - (red[0] + red[1])) / cnt;
        d_invd[g] = rsqrtf(PN_EPS + var);
    }
}

// ---------------- PairNorm apply -------------------------------------------
__global__ void __launch_bounds__(256) norm_kernel(const int* __restrict__ batch) {
    int idx = blockIdx.x * 256 + threadIdx.x;    // exactly NN*HV = 800000
    int row = idx >> 4, ln = idx & 15;
    int g = __ldg(batch + row);
    float4 hv = ((const float4*)d_h)[idx];
    float4 m = ((const float4*)d_mean)[g * HV + ln];
    float id = d_invd[g];
    hv.x = (hv.x - m.x) * id;
    hv.y = (hv.y - m.y) * id;
    hv.z = (hv.z - m.z) * id;
    hv.w = (hv.w - m.w) * id;
    ((float4*)d_h)[idx] = hv;
}

// ---------------- global add pool ------------------------------------------
__global__ void __launch_bounds__(256) pool_kernel(const int* __restrict__ batch) {
    int idx = blockIdx.x * 256 + threadIdx.x;    // NN*HV
    int row = idx >> 4, ln = idx & 15;
    int g = __ldg(batch + row);
    float4 hv = ((const float4*)d_h)[idx];
    red_add4(&((float4*)d_pool)[g * HV + ln], hv);
}

// ---------------- classifier; self-re-zeros pool ---------------------------
__global__ void cls_kernel(const float* __restrict__ W, const float* __restrict__ b,
                           float* __restrict__ out) {
    int g = blockIdx.x, c = threadIdx.x;     // 64 threads
    float p = d_pool[g * H + c];
    d_pool[g * H + c] = 0.f;
    float a = p * W[c * NOUT + 0];
    float bb = p * W[c * NOUT + 1];
    #pragma unroll
    for (int o = 16; o; o >>= 1) {
        a  += __shfl_down_sync(0xffffffffu, a, o);
        bb += __shfl_down_sync(0xffffffffu, bb, o);
    }
    __shared__ float sa[2], sb[2];
    if ((c & 31) == 0) { sa[c >> 5] = a; sb[c >> 5] = bb; }
    __syncthreads();
    if (c == 0) {
        out[g * NOUT + 0] = sa[0] + sa[1] + b[0];
        out[g * NOUT + 1] = sb[0] + sb[1] + b[1];
    }
}

// ---------------------------------------------------------------------------
extern "C" void kernel_launch(void* const* d_in, const int* in_sizes, int n_in,
                              void* d_out, int out_size) {
    const float* x        = (const float*)d_in[0];
    const int*   ei       = (const int*)  d_in[1];
    const float* eattr    = (const float*)d_in[2];
    const int*   batch    = (const int*)  d_in[3];
    const float* lin_W    = (const float*)d_in[4];
    const float* lin_b    = (const float*)d_in[5];
    const float* edge_W   = (const float*)d_in[6];
    const float* edge_b   = (const float*)d_in[7];
    const float* mlp_W1   = (const float*)d_in[8];
    const float* mlp_b1   = (const float*)d_in[9];
    const float* mbn_g    = (const float*)d_in[10];
    const float* mbn_b    = (const float*)d_in[11];
    const float* mbn_rm   = (const float*)d_in[12];
    const float* mbn_rv   = (const float*)d_in[13];
    const float* mlp_W2   = (const float*)d_in[14];
    const float* mlp_b2   = (const float*)d_in[15];
    const float* eps      = (const float*)d_in[16];
    const float* bn_g     = (const float*)d_in[17];
    const float* bn_b     = (const float*)d_in[18];
    const float* bn_rm    = (const float*)d_in[19];
    const float* bn_rv    = (const float*)d_in[20];
    const float* cls_W    = (const float*)d_in[21];
    const float* cls_b    = (const float*)d_in[22];
    float* out = (float*)d_out;

    count_kernel<<<2, 256>>>(batch);
    lin_in_kernel<<<NPAD / 16, 256>>>(x, lin_W, lin_b);

    for (int i = 0; i < NL; i++) {
        edge_kernel<<<NE / 16, 256>>>(ei, eattr, edge_W + i * EDIM * H, edge_b + i * H);
        int do_pn = (i < NL - 1) ? 1 : 0;
        mlp_kernel<<<NPAD / 32, 256>>>(
            mlp_W1 + i * H * H, mlp_b1 + i * H,
            mbn_g + i * H, mbn_b + i * H, mbn_rm + i * H, mbn_rv + i * H,
            mlp_W2 + i * H * H, mlp_b2 + i * H,
            bn_g + i * H, bn_b + i * H, bn_rm + i * H, bn_rv + i * H,
            eps + i, batch, do_pn);
        if (do_pn) {
            meaninv_kernel<<<NG, H>>>();
            norm_kernel<<<(NN * HV) / 256, 256>>>(batch);
        }
    }

    pool_kernel<<<(NN * HV) / 256, 256>>>(batch);
    cls_kernel<<<NG, H>>>(cls_W, cls_b, out);
}

// round 5
// speedup vs baseline: 1.0451x; 1.0451x over previous
#include <cuda_runtime.h>
#include <math.h>

#define NN    50000
#define NE    800000
#define INF_  32
#define H     64
#define HV    16      // H/4 (float4 lanes per row)
#define EDIM  4
#define NL    3
#define NG    512
#define NOUT  2
#define NPAD  50048   // 782 * 64
#define BN_EPS 1e-5f
#define PN_EPS 1e-5f

// dynamic smem layout for mlp_kernel (floats):
// [0,4096)      W1s
// [4096,8192)   W2s
// [8192,12288)  zs (64 rows x 64 cols)
// [12288,12352) s1s  [12352,12416) bb1  [12416,12480) s2s  [12480,12544) bb2
#define MLP_SMEM_FLOATS 12544
#define MLP_SMEM_BYTES  (MLP_SMEM_FLOATS * 4)

// ---------------- persistent device scratch (zero-initialized at load) -----
__device__ float d_h[NPAD * H];
__device__ float d_agg[NPAD * H];
__device__ float d_gsum[NG * H];
__device__ float d_gss[NG];
__device__ float d_gcnt[NG];
__device__ float d_mean[NG * H];
__device__ float d_invd[NG];
__device__ float d_pool[NG * H];

// 16-byte vector reduction to global (sm_90+)
__device__ __forceinline__ void red_add4(float4* a, float4 v) {
    asm volatile("red.global.add.v4.f32 [%0], {%1,%2,%3,%4};"
                 :: "l"(a), "f"(v.x), "f"(v.y), "f"(v.z), "f"(v.w) : "memory");
}

__device__ __forceinline__ float4 f4zero() { return make_float4(0.f, 0.f, 0.f, 0.f); }

__device__ __forceinline__ void f4fma(float4& acc, float s, const float4 w) {
    acc.x = fmaf(s, w.x, acc.x);
    acc.y = fmaf(s, w.y, acc.y);
    acc.z = fmaf(s, w.z, acc.z);
    acc.w = fmaf(s, w.w, acc.w);
}

__device__ __forceinline__ float4 f4relu_add(float4 a, float4 b) {
    return make_float4(fmaxf(a.x + b.x, 0.f), fmaxf(a.y + b.y, 0.f),
                       fmaxf(a.z + b.z, 0.f), fmaxf(a.w + b.w, 0.f));
}

// ---------------- counts: batch is sorted -> binary search per graph -------
__global__ void count_kernel(const int* __restrict__ batch) {
    int g = blockIdx.x * blockDim.x + threadIdx.x;
    if (g >= NG) return;
    int lo = 0, hi = NN;
    while (lo < hi) { int m = (lo + hi) >> 1; if (batch[m] < g) lo = m + 1; else hi = m; }
    int s = lo;
    lo = 0; hi = NN;
    while (lo < hi) { int m = (lo + hi) >> 1; if (batch[m] < g + 1) lo = m + 1; else hi = m; }
    d_gcnt[g] = fmaxf((float)(lo - s), 1.0f);
}

// ---------------- input linear: h = x @ W_in + b ; also zeroes d_agg -------
__global__ void __launch_bounds__(256) lin_in_kernel(const float* __restrict__ x,
                                                     const float* __restrict__ W,
                                                     const float* __restrict__ b) {
    __shared__ __align__(16) float4 Ws[INF_ * HV];
    __shared__ __align__(16) float4 bs[HV];
    int t = threadIdx.x;
    for (int j = t; j < INF_ * HV; j += 256) Ws[j] = ((const float4*)W)[j];
    if (t < HV) bs[t] = ((const float4*)b)[t];
    __syncthreads();

    int lane = t & 15, rloc = t >> 4;
    int row = blockIdx.x * 16 + rloc;       // row < NPAD always (3128*16 = 50048)

    ((float4*)d_agg)[row * HV + lane] = f4zero();   // zero agg for layer 0

    if (row < NN) {
        float4 acc = bs[lane];
        const float* xr = x + row * INF_;
        #pragma unroll
        for (int k = 0; k < INF_; k++) {
            float xv = __ldg(xr + k);
            f4fma(acc, xv, Ws[k * HV + lane]);
        }
        ((float4*)d_h)[row * HV + lane] = acc;
    }
}

// ---------------- edge kernel: agg[dst] += relu(h[src] + ea @ We + be) ------
__global__ void __launch_bounds__(256) edge_kernel(const int* __restrict__ ei,
                                                   const float* __restrict__ eattr,
                                                   const float* __restrict__ eW,
                                                   const float* __restrict__ eb) {
    __shared__ __align__(16) float4 Ws[EDIM * HV];
    __shared__ __align__(16) float4 bs[HV];
    int t = threadIdx.x;
    if (t < EDIM * HV) Ws[t] = ((const float4*)eW)[t];
    if (t < HV) bs[t] = ((const float4*)eb)[t];
    __syncthreads();

    int e    = blockIdx.x * 16 + (t >> 4);  // exactly NE = 50000*16 edges
    int lane = t & 15;
    int src = __ldg(ei + e);
    int dst = __ldg(ei + NE + e);
    float4 a = __ldg((const float4*)eattr + e);

    float4 v = bs[lane];
    f4fma(v, a.x, Ws[0 * HV + lane]);
    f4fma(v, a.y, Ws[1 * HV + lane]);
    f4fma(v, a.z, Ws[2 * HV + lane]);
    f4fma(v, a.w, Ws[3 * HV + lane]);

    float4 hv = __ldg((const float4*)d_h + src * HV + lane);
    float4 m = f4relu_add(v, hv);
    red_add4((float4*)d_agg + dst * HV + lane, m);
}

// ---------------- fused node MLP (+BN folded) + PairNorm stats -------------
// 64-row tile, each thread computes a 4-row x 4-col patch.
// z = (1+eps)*h + agg ; t = relu(BN1(z@W1+b1)) ; h' = relu(BN2(t@W2+b2))
__global__ void __launch_bounds__(256) mlp_kernel(
    const float* __restrict__ W1, const float* __restrict__ b1,
    const float* __restrict__ g1, const float* __restrict__ be1,
    const float* __restrict__ rm1, const float* __restrict__ rv1,
    const float* __restrict__ W2, const float* __restrict__ b2,
    const float* __restrict__ g2, const float* __restrict__ be2,
    const float* __restrict__ rm2, const float* __restrict__ rv2,
    const float* __restrict__ epsp, const int* __restrict__ batch, int do_pn)
{
    extern __shared__ __align__(16) float smem[];
    float* W1s = smem;               // [H*H]
    float* W2s = smem + 4096;        // [H*H]
    float* zs  = smem + 8192;        // [64][H]
    float* s1s = smem + 12288;
    float* bb1 = smem + 12352;
    float* s2s = smem + 12416;
    float* bb2 = smem + 12480;

    int t = threadIdx.x;
    if (t < H) {
        float s1 = g1[t] * rsqrtf(rv1[t] + BN_EPS);
        s1s[t] = s1;
        bb1[t] = b1[t] * s1 + be1[t] - rm1[t] * s1;
        float s2 = g2[t] * rsqrtf(rv2[t] + BN_EPS);
        s2s[t] = s2;
        bb2[t] = b2[t] * s2 + be2[t] - rm2[t] * s2;
    }
    __syncthreads();
    for (int j = t; j < H * H; j += 256) {
        int c = j & 63;
        W1s[j] = W1[j] * s1s[c];
        W2s[j] = W2[j] * s2s[c];
    }

    // stage z = (1+eps)*h + agg for 64 rows; re-zero agg for next layer
    float epv = 1.0f + epsp[0];
    int R0 = blockIdx.x * 64;
    for (int j = t; j < 64 * HV; j += 256) {
        int r = j >> 4, ln = j & 15;
        int gi = (R0 + r) * HV + ln;
        float4 hv = ((const float4*)d_h)[gi];
        float4 av = ((const float4*)d_agg)[gi];
        float4 z = make_float4(fmaf(epv, hv.x, av.x), fmaf(epv, hv.y, av.y),
                               fmaf(epv, hv.z, av.z), fmaf(epv, hv.w, av.w));
        *(float4*)&zs[r * H + ln * 4] = z;
        if (do_pn) ((float4*)d_agg)[gi] = f4zero();
    }
    __syncthreads();

    int c4 = t & 15;            // column group: cols c4*4 .. c4*4+3
    int rg = t >> 4;            // row group:   rows rg*4 .. rg*4+3

    // ---- GEMM1 (BN1 folded) + ReLU: 4x4 register patch ----
    float4 acc0 = f4zero(), acc1 = f4zero(), acc2 = f4zero(), acc3 = f4zero();
    #pragma unroll
    for (int k4 = 0; k4 < 16; k4++) {
        float4 w0 = *(const float4*)&W1s[(k4 * 4 + 0) * H + c4 * 4];
        float4 w1 = *(const float4*)&W1s[(k4 * 4 + 1) * H + c4 * 4];
        float4 w2 = *(const float4*)&W1s[(k4 * 4 + 2) * H + c4 * 4];
        float4 w3 = *(const float4*)&W1s[(k4 * 4 + 3) * H + c4 * 4];
        float4 z0 = *(const float4*)&zs[(rg * 4 + 0) * H + k4 * 4];
        float4 z1 = *(const float4*)&zs[(rg * 4 + 1) * H + k4 * 4];
        float4 z2 = *(const float4*)&zs[(rg * 4 + 2) * H + k4 * 4];
        float4 z3 = *(const float4*)&zs[(rg * 4 + 3) * H + k4 * 4];
        f4fma(acc0, z0.x, w0); f4fma(acc0, z0.y, w1); f4fma(acc0, z0.z, w2); f4fma(acc0, z0.w, w3);
        f4fma(acc1, z1.x, w0); f4fma(acc1, z1.y, w1); f4fma(acc1, z1.z, w2); f4fma(acc1, z1.w, w3);
        f4fma(acc2, z2.x, w0); f4fma(acc2, z2.y, w1); f4fma(acc2, z2.z, w2); f4fma(acc2, z2.w, w3);
        f4fma(acc3, z3.x, w0); f4fma(acc3, z3.y, w1); f4fma(acc3, z3.z, w2); f4fma(acc3, z3.w, w3);
    }
    float4 bv1 = *(const float4*)&bb1[c4 * 4];
    float4 t0 = f4relu_add(acc0, bv1);
    float4 t1 = f4relu_add(acc1, bv1);
    float4 t2 = f4relu_add(acc2, bv1);
    float4 t3 = f4relu_add(acc3, bv1);
    __syncthreads();                         // everyone done reading zs
    *(float4*)&zs[(rg * 4 + 0) * H + c4 * 4] = t0;
    *(float4*)&zs[(rg * 4 + 1) * H + c4 * 4] = t1;
    *(float4*)&zs[(rg * 4 + 2) * H + c4 * 4] = t2;
    *(float4*)&zs[(rg * 4 + 3) * H + c4 * 4] = t3;
    __syncthreads();

    // ---- GEMM2 (BN2 folded) + ReLU ----
    acc0 = f4zero(); acc1 = f4zero(); acc2 = f4zero(); acc3 = f4zero();
    #pragma unroll
    for (int k4 = 0; k4 < 16; k4++) {
        float4 w0 = *(const float4*)&W2s[(k4 * 4 + 0) * H + c4 * 4];
        float4 w1 = *(const float4*)&W2s[(k4 * 4 + 1) * H + c4 * 4];
        float4 w2 = *(const float4*)&W2s[(k4 * 4 + 2) * H + c4 * 4];
        float4 w3 = *(const float4*)&W2s[(k4 * 4 + 3) * H + c4 * 4];
        float4 z0 = *(const float4*)&zs[(rg * 4 + 0) * H + k4 * 4];
        float4 z1 = *(const float4*)&zs[(rg * 4 + 1) * H + k4 * 4];
        float4 z2 = *(const float4*)&zs[(rg * 4 + 2) * H + k4 * 4];
        float4 z3 = *(const float4*)&zs[(rg * 4 + 3) * H + k4 * 4];
        f4fma(acc0, z0.x, w0); f4fma(acc0, z0.y, w1); f4fma(acc0, z0.z, w2); f4fma(acc0, z0.w, w3);
        f4fma(acc1, z1.x, w0); f4fma(acc1, z1.y, w1); f4fma(acc1, z1.z, w2); f4fma(acc1, z1.w, w3);
        f4fma(acc2, z2.x, w0); f4fma(acc2, z2.y, w1); f4fma(acc2, z2.z, w2); f4fma(acc2, z2.w, w3);
        f4fma(acc3, z3.x, w0); f4fma(acc3, z3.y, w1); f4fma(acc3, z3.z, w2); f4fma(acc3, z3.w, w3);
    }
    float4 bv2 = *(const float4*)&bb2[c4 * 4];
    float4 h0 = f4relu_add(acc0, bv2);
    float4 h1 = f4relu_add(acc1, bv2);
    float4 h2 = f4relu_add(acc2, bv2);
    float4 h3 = f4relu_add(acc3, bv2);

    int row0 = R0 + rg * 4;
    float4 hr[4] = {h0, h1, h2, h3};
    #pragma unroll
    for (int r = 0; r < 4; r++) {
        int row = row0 + r;
        if (row < NN) ((float4*)d_h)[row * HV + c4] = hr[r];
    }

    if (do_pn) {
        #pragma unroll
        for (int r = 0; r < 4; r++) {
            int row = row0 + r;
            int gg = (row < NN) ? batch[row] : 0;
            if (row < NN) red_add4(&((float4*)d_gsum)[gg * HV + c4], hr[r]);
            float v = (row < NN) ? (hr[r].x*hr[r].x + hr[r].y*hr[r].y +
                                    hr[r].z*hr[r].z + hr[r].w*hr[r].w) : 0.f;
            #pragma unroll
            for (int o = 1; o < 16; o <<= 1) v += __shfl_xor_sync(0xffffffffu, v, o);
            if (c4 == 0 && row < NN) atomicAdd(&d_gss[gg], v);
        }
    }
}

// ---------------- PairNorm per-graph mean & inverse denom; self-re-zeros ---
__global__ void meaninv_kernel() {
    int g = blockIdx.x, c = threadIdx.x;     // 64 threads
    float cnt = d_gcnt[g];
    float s = d_gsum[g * H + c];
    d_gsum[g * H + c] = 0.f;
    float mean = s / cnt;
    d_mean[g * H + c] = mean;
    float part = mean * s;                    // sum_c (sum_h_c)^2 / cnt
    #pragma unroll
    for (int o = 16; o; o >>= 1) part += __shfl_down_sync(0xffffffffu, part, o);
    __shared__ float red[2];
    if ((c & 31) == 0) red[c >> 5] = part;
    __syncthreads();
    if (c == 0) {
        float ss = d_gss[g];
        d_gss[g] = 0.f;
        float var = (ss - (red[0] + red[1])) / cnt;
        d_invd[g] = rsqrtf(PN_EPS + var);
    }
}

// ---------------- PairNorm apply -------------------------------------------
__global__ void __launch_bounds__(256) norm_kernel(const int* __restrict__ batch) {
    int idx = blockIdx.x * 256 + threadIdx.x;    // exactly NN*HV = 800000
    int row = idx >> 4, ln = idx & 15;
    int g = __ldg(batch + row);
    float4 hv = ((const float4*)d_h)[idx];
    float4 m = ((const float4*)d_mean)[g * HV + ln];
    float id = d_invd[g];
    hv.x = (hv.x - m.x) * id;
    hv.y = (hv.y - m.y) * id;
    hv.z = (hv.z - m.z) * id;
    hv.w = (hv.w - m.w) * id;
    ((float4*)d_h)[idx] = hv;
}

// ---------------- global add pool ------------------------------------------
__global__ void __launch_bounds__(256) pool_kernel(const int* __restrict__ batch) {
    int idx = blockIdx.x * 256 + threadIdx.x;    // NN*HV
    int row = idx >> 4, ln = idx & 15;
    int g = __ldg(batch + row);
    float4 hv = ((const float4*)d_h)[idx];
    red_add4(&((float4*)d_pool)[g * HV + ln], hv);
}

// ---------------- classifier; self-re-zeros pool ---------------------------
__global__ void cls_kernel(const float* __restrict__ W, const float* __restrict__ b,
                           float* __restrict__ out) {
    int g = blockIdx.x, c = threadIdx.x;     // 64 threads
    float p = d_pool[g * H + c];
    d_pool[g * H + c] = 0.f;
    float a = p * W[c * NOUT + 0];
    float bb = p * W[c * NOUT + 1];
    #pragma unroll
    for (int o = 16; o; o >>= 1) {
        a  += __shfl_down_sync(0xffffffffu, a, o);
        bb += __shfl_down_sync(0xffffffffu, bb, o);
    }
    __shared__ float sa[2], sb[2];
    if ((c & 31) == 0) { sa[c >> 5] = a; sb[c >> 5] = bb; }
    __syncthreads();
    if (c == 0) {
        out[g * NOUT + 0] = sa[0] + sa[1] + b[0];
        out[g * NOUT + 1] = sb[0] + sb[1] + b[1];
    }
}

// ---------------------------------------------------------------------------
extern "C" void kernel_launch(void* const* d_in, const int* in_sizes, int n_in,
                              void* d_out, int out_size) {
    const float* x        = (const float*)d_in[0];
    const int*   ei       = (const int*)  d_in[1];
    const float* eattr    = (const float*)d_in[2];
    const int*   batch    = (const int*)  d_in[3];
    const float* lin_W    = (const float*)d_in[4];
    const float* lin_b    = (const float*)d_in[5];
    const float* edge_W   = (const float*)d_in[6];
    const float* edge_b   = (const float*)d_in[7];
    const float* mlp_W1   = (const float*)d_in[8];
    const float* mlp_b1   = (const float*)d_in[9];
    const float* mbn_g    = (const float*)d_in[10];
    const float* mbn_b    = (const float*)d_in[11];
    const float* mbn_rm   = (const float*)d_in[12];
    const float* mbn_rv   = (const float*)d_in[13];
    const float* mlp_W2   = (const float*)d_in[14];
    const float* mlp_b2   = (const float*)d_in[15];
    const float* eps      = (const float*)d_in[16];
    const float* bn_g     = (const float*)d_in[17];
    const float* bn_b     = (const float*)d_in[18];
    const float* bn_rm    = (const float*)d_in[19];
    const float* bn_rv    = (const float*)d_in[20];
    const float* cls_W    = (const float*)d_in[21];
    const float* cls_b    = (const float*)d_in[22];
    float* out = (float*)d_out;

    cudaFuncSetAttribute(mlp_kernel, cudaFuncAttributeMaxDynamicSharedMemorySize,
                         MLP_SMEM_BYTES);

    count_kernel<<<2, 256>>>(batch);
    lin_in_kernel<<<NPAD / 16, 256>>>(x, lin_W, lin_b);

    for (int i = 0; i < NL; i++) {
        edge_kernel<<<NE / 16, 256>>>(ei, eattr, edge_W + i * EDIM * H, edge_b + i * H);
        int do_pn = (i < NL - 1) ? 1 : 0;
        mlp_kernel<<<NPAD / 64, 256, MLP_SMEM_BYTES>>>(
            mlp_W1 + i * H * H, mlp_b1 + i * H,
            mbn_g + i * H, mbn_b + i * H, mbn_rm + i * H, mbn_rv + i * H,
            mlp_W2 + i * H * H, mlp_b2 + i * H,
            bn_g + i * H, bn_b + i * H, bn_rm + i * H, bn_rv + i * H,
            eps + i, batch, do_pn);
        if (do_pn) {
            meaninv_kernel<<<NG, H>>>();
            norm_kernel<<<(NN * HV) / 256, 256>>>(batch);
        }
    }

    pool_kernel<<<(NN * HV) / 256, 256>>>(batch);
    cls_kernel<<<NG, H>>>(cls_W, cls_b, out);
}

// round 6
// speedup vs baseline: 1.1493x; 1.0996x over previous
#include <cuda_runtime.h>
#include <math.h>

#define NN    50000
#define NE    800000
#define INF_  32
#define H     64
#define HV    16      // H/4 (float4 lanes per row)
#define EDIM  4
#define NL    3
#define NG    512
#define NOUT  2
#define NPAD  50048   // 782 * 64
#define BN_EPS 1e-5f
#define PN_EPS 1e-5f

// ---------------- persistent device scratch (zero-initialized at load) -----
__device__ float d_h[NPAD * H];
__device__ float d_agg[NPAD * H];
__device__ float d_tmp[NPAD * H];
__device__ float d_gsum[NG * H];
__device__ float d_gss[NG];
__device__ float d_gcnt[NG];
__device__ float d_mean[NG * H];
__device__ float d_invd[NG];
__device__ float d_pool[NG * H];

// 16-byte vector reduction to global (sm_90+)
__device__ __forceinline__ void red_add4(float4* a, float4 v) {
    asm volatile("red.global.add.v4.f32 [%0], {%1,%2,%3,%4};"
                 :: "l"(a), "f"(v.x), "f"(v.y), "f"(v.z), "f"(v.w) : "memory");
}

__device__ __forceinline__ float4 f4zero() { return make_float4(0.f, 0.f, 0.f, 0.f); }

__device__ __forceinline__ void f4fma(float4& acc, float s, const float4 w) {
    acc.x = fmaf(s, w.x, acc.x);
    acc.y = fmaf(s, w.y, acc.y);
    acc.z = fmaf(s, w.z, acc.z);
    acc.w = fmaf(s, w.w, acc.w);
}

__device__ __forceinline__ float4 f4relu_add(float4 a, float4 b) {
    return make_float4(fmaxf(a.x + b.x, 0.f), fmaxf(a.y + b.y, 0.f),
                       fmaxf(a.z + b.z, 0.f), fmaxf(a.w + b.w, 0.f));
}

// 4x4 register-patch GEMM over 64x64 tile in smem. Thread t: cols (t&15)*4..+3,
// rows (t>>4)*4..+3. acc[r] = sum_k zrow[r][k] * W[k][cols].
__device__ __forceinline__ void gemm64(const float* __restrict__ Ws,
                                       const float* __restrict__ zs,
                                       int rg, int c4, float4 acc[4]) {
    acc[0] = f4zero(); acc[1] = f4zero(); acc[2] = f4zero(); acc[3] = f4zero();
    #pragma unroll
    for (int k4 = 0; k4 < 16; k4++) {
        float4 w0 = *(const float4*)&Ws[(k4 * 4 + 0) * H + c4 * 4];
        float4 w1 = *(const float4*)&Ws[(k4 * 4 + 1) * H + c4 * 4];
        float4 w2 = *(const float4*)&Ws[(k4 * 4 + 2) * H + c4 * 4];
        float4 w3 = *(const float4*)&Ws[(k4 * 4 + 3) * H + c4 * 4];
        float4 z0 = *(const float4*)&zs[(rg * 4 + 0) * H + k4 * 4];
        float4 z1 = *(const float4*)&zs[(rg * 4 + 1) * H + k4 * 4];
        float4 z2 = *(const float4*)&zs[(rg * 4 + 2) * H + k4 * 4];
        float4 z3 = *(const float4*)&zs[(rg * 4 + 3) * H + k4 * 4];
        f4fma(acc[0], z0.x, w0); f4fma(acc[0], z0.y, w1); f4fma(acc[0], z0.z, w2); f4fma(acc[0], z0.w, w3);
        f4fma(acc[1], z1.x, w0); f4fma(acc[1], z1.y, w1); f4fma(acc[1], z1.z, w2); f4fma(acc[1], z1.w, w3);
        f4fma(acc[2], z2.x, w0); f4fma(acc[2], z2.y, w1); f4fma(acc[2], z2.z, w2); f4fma(acc[2], z2.w, w3);
        f4fma(acc[3], z3.x, w0); f4fma(acc[3], z3.y, w1); f4fma(acc[3], z3.z, w2); f4fma(acc[3], z3.w, w3);
    }
}

// ---------------- counts: batch is sorted -> binary search per graph -------
__global__ void count_kernel(const int* __restrict__ batch) {
    int g = blockIdx.x * blockDim.x + threadIdx.x;
    if (g >= NG) return;
    int lo = 0, hi = NN;
    while (lo < hi) { int m = (lo + hi) >> 1; if (batch[m] < g) lo = m + 1; else hi = m; }
    int s = lo;
    lo = 0; hi = NN;
    while (lo < hi) { int m = (lo + hi) >> 1; if (batch[m] < g + 1) lo = m + 1; else hi = m; }
    d_gcnt[g] = fmaxf((float)(lo - s), 1.0f);
}

// ---------------- input linear: h = x @ W_in + b ; also zeroes d_agg -------
__global__ void __launch_bounds__(256) lin_in_kernel(const float* __restrict__ x,
                                                     const float* __restrict__ W,
                                                     const float* __restrict__ b) {
    __shared__ __align__(16) float4 Ws[INF_ * HV];
    __shared__ __align__(16) float4 bs[HV];
    int t = threadIdx.x;
    for (int j = t; j < INF_ * HV; j += 256) Ws[j] = ((const float4*)W)[j];
    if (t < HV) bs[t] = ((const float4*)b)[t];
    __syncthreads();

    int lane = t & 15, rloc = t >> 4;
    int row = blockIdx.x * 16 + rloc;       // row < NPAD always (3128*16 = 50048)

    ((float4*)d_agg)[row * HV + lane] = f4zero();   // zero agg for layer 0

    if (row < NN) {
        float4 acc = bs[lane];
        const float* xr = x + row * INF_;
        #pragma unroll
        for (int k = 0; k < INF_; k++) {
            float xv = __ldg(xr + k);
            f4fma(acc, xv, Ws[k * HV + lane]);
        }
        ((float4*)d_h)[row * HV + lane] = acc;
    }
}

// ---------------- edge kernel: agg[dst] += relu(h[src] + ea @ We + be) ------
__global__ void __launch_bounds__(256) edge_kernel(const int* __restrict__ ei,
                                                   const float* __restrict__ eattr,
                                                   const float* __restrict__ eW,
                                                   const float* __restrict__ eb) {
    __shared__ __align__(16) float4 Ws[EDIM * HV];
    __shared__ __align__(16) float4 bs[HV];
    int t = threadIdx.x;
    if (t < EDIM * HV) Ws[t] = ((const float4*)eW)[t];
    if (t < HV) bs[t] = ((const float4*)eb)[t];
    __syncthreads();

    int e    = blockIdx.x * 16 + (t >> 4);  // exactly NE = 50000*16 edges
    int lane = t & 15;
    int src = __ldg(ei + e);
    int dst = __ldg(ei + NE + e);
    float4 a = __ldg((const float4*)eattr + e);

    float4 v = bs[lane];
    f4fma(v, a.x, Ws[0 * HV + lane]);
    f4fma(v, a.y, Ws[1 * HV + lane]);
    f4fma(v, a.z, Ws[2 * HV + lane]);
    f4fma(v, a.w, Ws[3 * HV + lane]);

    float4 hv = __ldg((const float4*)d_h + src * HV + lane);
    float4 m = f4relu_add(v, hv);
    red_add4((float4*)d_agg + dst * HV + lane, m);
}

// ---------------- MLP stage 1: d_tmp = relu(BN1(z @ W1 + b1)) --------------
// z = (1+eps)*h + agg, computed on the fly; optionally re-zeros d_agg.
// Single barrier; all global loads batched up front; BN params per-thread.
__global__ void __launch_bounds__(256) mlp1_kernel(
    const float* __restrict__ W1, const float* __restrict__ b1,
    const float* __restrict__ g1, const float* __restrict__ be1,
    const float* __restrict__ rm1, const float* __restrict__ rv1,
    const float* __restrict__ epsp, int do_zero)
{
    __shared__ __align__(16) float Ws[H * H];
    __shared__ __align__(16) float zs[64 * H];

    int t = threadIdx.x;
    int c4 = t & 15, rg = t >> 4;
    int c0 = c4 * 4;
    int R0 = blockIdx.x * 64;

    // --- batch all global loads (independent) ---
    float4 wv[4];
    #pragma unroll
    for (int s = 0; s < 4; s++) wv[s] = __ldg((const float4*)W1 + t + 256 * s);

    float4 gv  = __ldg((const float4*)(g1 + c0));
    float4 rvv = __ldg((const float4*)(rv1 + c0));
    float4 bv  = __ldg((const float4*)(b1 + c0));
    float4 bev = __ldg((const float4*)(be1 + c0));
    float4 rmv = __ldg((const float4*)(rm1 + c0));
    float epv = 1.0f + __ldg(epsp);

    float4 zst[4];
    #pragma unroll
    for (int s = 0; s < 4; s++) {
        int j = t + 256 * s;                    // j = r*16 + ln
        int gi = R0 * HV + j;
        float4 hv = __ldg((const float4*)d_h + gi);
        float4 av = __ldg((const float4*)d_agg + gi);
        zst[s] = make_float4(fmaf(epv, hv.x, av.x), fmaf(epv, hv.y, av.y),
                             fmaf(epv, hv.z, av.z), fmaf(epv, hv.w, av.w));
        if (do_zero) ((float4*)d_agg)[gi] = f4zero();
    }

    // per-thread BN fold for own 4 columns
    float4 sc, bb;
    sc.x = gv.x * rsqrtf(rvv.x + BN_EPS);
    sc.y = gv.y * rsqrtf(rvv.y + BN_EPS);
    sc.z = gv.z * rsqrtf(rvv.z + BN_EPS);
    sc.w = gv.w * rsqrtf(rvv.w + BN_EPS);
    bb.x = fmaf(bv.x - rmv.x, sc.x, bev.x);
    bb.y = fmaf(bv.y - rmv.y, sc.y, bev.y);
    bb.z = fmaf(bv.z - rmv.z, sc.z, bev.z);
    bb.w = fmaf(bv.w - rmv.w, sc.w, bev.w);

    // scale W columns (W float4 j4 = t+256s covers cols c0..c0+3 for all s)
    #pragma unroll
    for (int s = 0; s < 4; s++) {
        float4 w = wv[s];
        w.x *= sc.x; w.y *= sc.y; w.z *= sc.z; w.w *= sc.w;
        ((float4*)Ws)[t + 256 * s] = w;
        ((float4*)zs)[t + 256 * s] = zst[s];
    }
    __syncthreads();

    float4 acc[4];
    gemm64(Ws, zs, rg, c4, acc);

    int row0 = R0 + rg * 4;
    #pragma unroll
    for (int r = 0; r < 4; r++) {
        int row = row0 + r;
        if (row < NN) ((float4*)d_tmp)[row * HV + c4] = f4relu_add(acc[r], bb);
    }
}

// ---------------- MLP stage 2: d_h = relu(BN2(y @ W2 + b2)) + PN stats -----
__global__ void __launch_bounds__(256) mlp2_kernel(
    const float* __restrict__ W2, const float* __restrict__ b2,
    const float* __restrict__ g2, const float* __restrict__ be2,
    const float* __restrict__ rm2, const float* __restrict__ rv2,
    const int* __restrict__ batch, int do_pn)
{
    __shared__ __align__(16) float Ws[H * H];
    __shared__ __align__(16) float zs[64 * H];

    int t = threadIdx.x;
    int c4 = t & 15, rg = t >> 4;
    int c0 = c4 * 4;
    int R0 = blockIdx.x * 64;

    float4 wv[4];
    #pragma unroll
    for (int s = 0; s < 4; s++) wv[s] = __ldg((const float4*)W2 + t + 256 * s);

    float4 gv  = __ldg((const float4*)(g2 + c0));
    float4 rvv = __ldg((const float4*)(rv2 + c0));
    float4 bv  = __ldg((const float4*)(b2 + c0));
    float4 bev = __ldg((const float4*)(be2 + c0));
    float4 rmv = __ldg((const float4*)(rm2 + c0));

    float4 zst[4];
    #pragma unroll
    for (int s = 0; s < 4; s++) {
        int j = t + 256 * s;
        zst[s] = __ldg((const float4*)d_tmp + R0 * HV + j);
    }

    float4 sc, bb;
    sc.x = gv.x * rsqrtf(rvv.x + BN_EPS);
    sc.y = gv.y * rsqrtf(rvv.y + BN_EPS);
    sc.z = gv.z * rsqrtf(rvv.z + BN_EPS);
    sc.w = gv.w * rsqrtf(rvv.w + BN_EPS);
    bb.x = fmaf(bv.x - rmv.x, sc.x, bev.x);
    bb.y = fmaf(bv.y - rmv.y, sc.y, bev.y);
    bb.z = fmaf(bv.z - rmv.z, sc.z, bev.z);
    bb.w = fmaf(bv.w - rmv.w, sc.w, bev.w);

    #pragma unroll
    for (int s = 0; s < 4; s++) {
        float4 w = wv[s];
        w.x *= sc.x; w.y *= sc.y; w.z *= sc.z; w.w *= sc.w;
        ((float4*)Ws)[t + 256 * s] = w;
        ((float4*)zs)[t + 256 * s] = zst[s];
    }
    __syncthreads();

    float4 acc[4];
    gemm64(Ws, zs, rg, c4, acc);

    int row0 = R0 + rg * 4;
    #pragma unroll
    for (int r = 0; r < 4; r++) {
        int row = row0 + r;
        float4 hv = f4relu_add(acc[r], bb);
        if (row < NN) ((float4*)d_h)[row * HV + c4] = hv;
        if (do_pn) {
            int gg = (row < NN) ? __ldg(batch + row) : 0;
            if (row < NN) red_add4(&((float4*)d_gsum)[gg * HV + c4], hv);
            float v = (row < NN) ? (hv.x*hv.x + hv.y*hv.y + hv.z*hv.z + hv.w*hv.w) : 0.f;
            #pragma unroll
            for (int o = 1; o < 16; o <<= 1) v += __shfl_xor_sync(0xffffffffu, v, o);
            if (c4 == 0 && row < NN) atomicAdd(&d_gss[gg], v);
        }
    }
}

// ---------------- PairNorm per-graph mean & inverse denom; self-re-zeros ---
__global__ void meaninv_kernel() {
    int g = blockIdx.x, c = threadIdx.x;     // 64 threads
    float cnt = d_gcnt[g];
    float s = d_gsum[g * H + c];
    d_gsum[g * H + c] = 0.f;
    float mean = s / cnt;
    d_mean[g * H + c] = mean;
    float part = mean * s;                    // sum_c (sum_h_c)^2 / cnt
    #pragma unroll
    for (int o = 16; o; o >>= 1) part += __shfl_down_sync(0xffffffffu, part, o);
    __shared__ float red[2];
    if ((c & 31) == 0) red[c >> 5] = part;
    __syncthreads();
    if (c == 0) {
        float ss = d_gss[g];
        d_gss[g] = 0.f;
        float var = (ss - (red[0] + red[1])) / cnt;
        d_invd[g] = rsqrtf(PN_EPS + var);
    }
}

// ---------------- PairNorm apply -------------------------------------------
__global__ void __launch_bounds__(256) norm_kernel(const int* __restrict__ batch) {
    int idx = blockIdx.x * 256 + threadIdx.x;    // exactly NN*HV = 800000
    int row = idx >> 4, ln = idx & 15;
    int g = __ldg(batch + row);
    float4 hv = ((const float4*)d_h)[idx];
    float4 m = ((const float4*)d_mean)[g * HV + ln];
    float id = d_invd[g];
    hv.x = (hv.x - m.x) * id;
    hv.y = (hv.y - m.y) * id;
    hv.z = (hv.z - m.z) * id;
    hv.w = (hv.w - m.w) * id;
    ((float4*)d_h)[idx] = hv;
}

// ---------------- global add pool ------------------------------------------
__global__ void __launch_bounds__(256) pool_kernel(const int* __restrict__ batch) {
    int idx = blockIdx.x * 256 + threadIdx.x;    // NN*HV
    int row = idx >> 4, ln = idx & 15;
    int g = __ldg(batch + row);
    float4 hv = ((const float4*)d_h)[idx];
    red_add4(&((float4*)d_pool)[g * HV + ln], hv);
}

// ---------------- classifier; self-re-zeros pool ---------------------------
__global__ void cls_kernel(const float* __restrict__ W, const float* __restrict__ b,
                           float* __restrict__ out) {
    int g = blockIdx.x, c = threadIdx.x;     // 64 threads
    float p = d_pool[g * H + c];
    d_pool[g * H + c] = 0.f;
    float a = p * W[c * NOUT + 0];
    float bb = p * W[c * NOUT + 1];
    #pragma unroll
    for (int o = 16; o; o >>= 1) {
        a  += __shfl_down_sync(0xffffffffu, a, o);
        bb += __shfl_down_sync(0xffffffffu, bb, o);
    }
    __shared__ float sa[2], sb[2];
    if ((c & 31) == 0) { sa[c >> 5] = a; sb[c >> 5] = bb; }
    __syncthreads();
    if (c == 0) {
        out[g * NOUT + 0] = sa[0] + sa[1] + b[0];
        out[g * NOUT + 1] = sb[0] + sb[1] + b[1];
    }
}

// ---------------------------------------------------------------------------
extern "C" void kernel_launch(void* const* d_in, const int* in_sizes, int n_in,
                              void* d_out, int out_size) {
    const float* x        = (const float*)d_in[0];
    const int*   ei       = (const int*)  d_in[1];
    const float* eattr    = (const float*)d_in[2];
    const int*   batch    = (const int*)  d_in[3];
    const float* lin_W    = (const float*)d_in[4];
    const float* lin_b    = (const float*)d_in[5];
    const float* edge_W   = (const float*)d_in[6];
    const float* edge_b   = (const float*)d_in[7];
    const float* mlp_W1   = (const float*)d_in[8];
    const float* mlp_b1   = (const float*)d_in[9];
    const float* mbn_g    = (const float*)d_in[10];
    const float* mbn_b    = (const float*)d_in[11];
    const float* mbn_rm   = (const float*)d_in[12];
    const float* mbn_rv   = (const float*)d_in[13];
    const float* mlp_W2   = (const float*)d_in[14];
    const float* mlp_b2   = (const float*)d_in[15];
    const float* eps      = (const float*)d_in[16];
    const float* bn_g     = (const float*)d_in[17];
    const float* bn_b     = (const float*)d_in[18];
    const float* bn_rm    = (const float*)d_in[19];
    const float* bn_rv    = (const float*)d_in[20];
    const float* cls_W    = (const float*)d_in[21];
    const float* cls_b    = (const float*)d_in[22];
    float* out = (float*)d_out;

    count_kernel<<<2, 256>>>(batch);
    lin_in_kernel<<<NPAD / 16, 256>>>(x, lin_W, lin_b);

    for (int i = 0; i < NL; i++) {
        edge_kernel<<<NE / 16, 256>>>(ei, eattr, edge_W + i * EDIM * H, edge_b + i * H);
        int do_pn = (i < NL - 1) ? 1 : 0;
        mlp1_kernel<<<NPAD / 64, 256>>>(
            mlp_W1 + i * H * H, mlp_b1 + i * H,
            mbn_g + i * H, mbn_b + i * H, mbn_rm + i * H, mbn_rv + i * H,
            eps + i, do_pn);
        mlp2_kernel<<<NPAD / 64, 256>>>(
            mlp_W2 + i * H * H, mlp_b2 + i * H,
            bn_g + i * H, bn_b + i * H, bn_rm + i * H, bn_rv + i * H,
            batch, do_pn);
        if (do_pn) {
            meaninv_kernel<<<NG, H>>>();
            norm_kernel<<<(NN * HV) / 256, 256>>>(batch);
        }
    }

    pool_kernel<<<(NN * HV) / 256, 256>>>(batch);
    cls_kernel<<<NG, H>>>(cls_W, cls_b, out);
}